// round 2
// baseline (speedup 1.0000x reference)
#include <cuda_runtime.h>
#include <math.h>

#define NQ 8
#define DIM 256
#define NL 6
#define MAXB 8192

// ---------------- scratch (static device globals; no runtime alloc) ----------
__device__ float2 g_U[NL * NQ * 4];          // combined per-(layer,qubit) 2x2 complex gates
__device__ float  g_q[MAXB * 4];             // quantum Z expectations
__device__ float  g_y1[MAXB * 32];           // pre-BN1 activations
__device__ float  g_y2[MAXB * 16];           // pre-BN2 activations
__device__ float  g_part1[(MAXB / 16) * 64]; // per-block BN1 partial sum/sumsq
__device__ float  g_bn1[64];                 // BN1 scale[32], shift[32]
__device__ float  g_part2[(MAXB / 256) * 32];// per-block BN2 partial sum/sumsq
__device__ float  g_bn2[32];                 // BN2 scale[16], shift[16]

__device__ __forceinline__ float2 cmul(float2 a, float2 b) {
    return make_float2(a.x * b.x - a.y * b.y, a.x * b.y + a.y * b.x);
}
__device__ __forceinline__ float2 cadd(float2 a, float2 b) {
    return make_float2(a.x + b.x, a.y + b.y);
}

// ---------------- K1: combined gate matrices U = RZ * RY * RX ----------------
__global__ void k_gates(const float* __restrict__ qw) {
    int g = threadIdx.x;
    if (g >= NL * NQ) return;
    int l = g >> 3, q = g & 7;
    float tx = 0.5f * qw[l * 24 + q * 3 + 0];
    float ty = 0.5f * qw[l * 24 + q * 3 + 1];
    float tz = 0.5f * qw[l * 24 + q * 3 + 2];
    float cx = cosf(tx), sx = sinf(tx);
    float cy = cosf(ty), sy = sinf(ty);
    float cz = cosf(tz), sz = sinf(tz);
    // RX = [[(cx,0),(0,-sx)],[(0,-sx),(cx,0)]]
    // RY = [[(cy,0),(-sy,0)],[(sy,0),(cy,0)]]
    // RZ = diag((cz,-sz),(cz,sz))
    float2 RX0 = make_float2(cx, 0.f), RX1 = make_float2(0.f, -sx);
    float2 RX2 = make_float2(0.f, -sx), RX3 = make_float2(cx, 0.f);
    float2 RY0 = make_float2(cy, 0.f), RY1 = make_float2(-sy, 0.f);
    float2 RY2 = make_float2(sy, 0.f), RY3 = make_float2(cy, 0.f);
    float2 RZ0 = make_float2(cz, -sz), RZ3 = make_float2(cz, sz);
    // M = RY @ RX
    float2 M0 = cadd(cmul(RY0, RX0), cmul(RY1, RX2));
    float2 M1 = cadd(cmul(RY0, RX1), cmul(RY1, RX3));
    float2 M2 = cadd(cmul(RY2, RX0), cmul(RY3, RX2));
    float2 M3 = cadd(cmul(RY2, RX1), cmul(RY3, RX3));
    // U = RZ @ M
    g_U[g * 4 + 0] = cmul(RZ0, M0);
    g_U[g * 4 + 1] = cmul(RZ0, M1);
    g_U[g * 4 + 2] = cmul(RZ3, M2);
    g_U[g * 4 + 3] = cmul(RZ3, M3);
}

// ---------------- K2: statevector simulation, one CTA per sample -------------
__global__ __launch_bounds__(128) void k_qsim(const float* __restrict__ x, int B) {
    __shared__ float2 st[DIM];
    __shared__ float2 gsh[NL * NQ * 4];
    __shared__ float  red[4];
    __shared__ float  r2[4][4];

    int b = blockIdx.x;
    int t = threadIdx.x; // 128 threads

    for (int i = t; i < NL * NQ * 4; i += 128) gsh[i] = g_U[i];

    const float2* xp = (const float2*)(x + (size_t)b * DIM);
    float2 v = xp[t];
    st[2 * t]     = make_float2(v.x, 0.f);
    st[2 * t + 1] = make_float2(v.y, 0.f);

    // ||x||^2 reduction (defer normalization: probs scale by 1/nrm2)
    float s = v.x * v.x + v.y * v.y;
    #pragma unroll
    for (int o = 16; o; o >>= 1) s += __shfl_xor_sync(0xffffffffu, s, o);
    if ((t & 31) == 0) red[t >> 5] = s;

    // Per-layer CNOT block = fixed permutation. new[i] = old[perm(i)],
    // perm = f1∘f2∘...∘f11 evaluated innermost-first (reverse gate order).
    // Forward gates (c,t): (0,1)(1,2)(2,3)(3,4)(4,5)(5,6)(6,7)(7,0)(0,2)(2,4)(4,6)
    // bit positions: cb = 7-c, tb = 7-t. Reverse order:
    const int cbs[11] = {3, 5, 7, 0, 1, 2, 3, 4, 5, 6, 7};
    const int tbs[11] = {1, 3, 5, 7, 0, 1, 2, 3, 4, 5, 6};
    int p0 = t, p1 = t + 128;
    #pragma unroll
    for (int gi = 0; gi < 11; gi++) {
        p0 ^= ((p0 >> cbs[gi]) & 1) << tbs[gi];
        p1 ^= ((p1 >> cbs[gi]) & 1) << tbs[gi];
    }

    __syncthreads();
    float nrm2 = red[0] + red[1] + red[2] + red[3];

    for (int l = 0; l < NL; l++) {
        #pragma unroll
        for (int q = 0; q < NQ; q++) {
            int bp = 7 - q;
            int mask = 1 << bp;
            int i0 = ((t >> bp) << (bp + 1)) | (t & (mask - 1));
            int i1 = i0 | mask;
            float2 a = st[i0], c = st[i1];
            const float2* U = &gsh[(l * 8 + q) * 4];
            float2 u0 = U[0], u1 = U[1], u2 = U[2], u3 = U[3];
            st[i0] = cadd(cmul(u0, a), cmul(u1, c));
            st[i1] = cadd(cmul(u2, a), cmul(u3, c));
            __syncthreads();
        }
        // CNOT block as permutation
        float2 t0 = st[p0], t1 = st[p1];
        __syncthreads();
        st[t]       = t0;
        st[t + 128] = t1;
        __syncthreads();
    }

    // Z expectations on wires 0..3 (bits 7..4)
    float e0 = 0.f, e1 = 0.f, e2 = 0.f, e3 = 0.f;
    #pragma unroll
    for (int r = 0; r < 2; r++) {
        int idx = t + r * 128;
        float2 a = st[idx];
        float p = a.x * a.x + a.y * a.y;
        e0 += (idx & 128) ? -p : p;
        e1 += (idx & 64)  ? -p : p;
        e2 += (idx & 32)  ? -p : p;
        e3 += (idx & 16)  ? -p : p;
    }
    #pragma unroll
    for (int o = 16; o; o >>= 1) {
        e0 += __shfl_xor_sync(0xffffffffu, e0, o);
        e1 += __shfl_xor_sync(0xffffffffu, e1, o);
        e2 += __shfl_xor_sync(0xffffffffu, e2, o);
        e3 += __shfl_xor_sync(0xffffffffu, e3, o);
    }
    if ((t & 31) == 0) {
        int w = t >> 5;
        r2[0][w] = e0; r2[1][w] = e1; r2[2][w] = e2; r2[3][w] = e3;
    }
    __syncthreads();
    if (t < 4)
        g_q[(size_t)b * 4 + t] = (r2[t][0] + r2[t][1] + r2[t][2] + r2[t][3]) / nrm2;
}

// ---------------- K3: feature processor + adapter + fc1 + BN1 partials -------
// 16 samples per block, 256 threads.
__global__ __launch_bounds__(256) void k_feat(
    const float* __restrict__ x,
    const float* __restrict__ aW, const float* __restrict__ ab,
    const float* __restrict__ fW1, const float* __restrict__ fb1,
    const float* __restrict__ fW2, const float* __restrict__ fb2,
    const float* __restrict__ cW1, const float* __restrict__ cb1, int B)
{
    __shared__ float xs[16][257];
    __shared__ float ws[64][65];
    __shared__ float h1s[16][65];
    __shared__ float hs[16][4];
    __shared__ float ys[16][33];
    __shared__ float fw2s[256], cw1s[128];
    __shared__ float fb2s[4], abs_[4], aWs[16], cb1s[32];

    int tid = threadIdx.x;
    int S0 = blockIdx.x * 16;

    for (int i = tid; i < 16 * 256; i += 256) {
        int s = i >> 8, k = i & 255;
        xs[s][k] = x[(size_t)(S0 + s) * 256 + k];
    }
    fw2s[tid] = fW2[tid];
    if (tid < 128) cw1s[tid] = cW1[tid];
    if (tid < 32)  cb1s[tid] = cb1[tid];
    if (tid < 16)  aWs[tid]  = aW[tid];
    if (tid < 4) { fb2s[tid] = fb2[tid]; abs_[tid] = ab[tid]; }

    int s  = tid & 15;
    int og = tid >> 4;
    float acc0 = 0.f, acc1 = 0.f, acc2 = 0.f, acc3 = 0.f;

    for (int kc = 0; kc < 4; kc++) {
        __syncthreads();
        for (int i = tid; i < 64 * 64; i += 256) {
            int o = i >> 6, k = i & 63;
            ws[o][k] = fW1[o * 256 + kc * 64 + k];
        }
        __syncthreads();
        #pragma unroll 8
        for (int k = 0; k < 64; k++) {
            float xv = xs[s][kc * 64 + k];
            acc0 += ws[og * 4 + 0][k] * xv;
            acc1 += ws[og * 4 + 1][k] * xv;
            acc2 += ws[og * 4 + 2][k] * xv;
            acc3 += ws[og * 4 + 3][k] * xv;
        }
    }
    h1s[s][og * 4 + 0] = fmaxf(acc0 + fb1[og * 4 + 0], 0.f);
    h1s[s][og * 4 + 1] = fmaxf(acc1 + fb1[og * 4 + 1], 0.f);
    h1s[s][og * 4 + 2] = fmaxf(acc2 + fb1[og * 4 + 2], 0.f);
    h1s[s][og * 4 + 3] = fmaxf(acc3 + fb1[og * 4 + 3], 0.f);
    __syncthreads();

    if (tid < 64) {
        int ss = tid & 15, j = tid >> 4;
        float a = fb2s[j];
        #pragma unroll 8
        for (int k = 0; k < 64; k++) a += h1s[ss][k] * fw2s[j * 64 + k];
        float cf = tanhf(a);
        float qf = abs_[j];
        #pragma unroll
        for (int k = 0; k < 4; k++) qf += aWs[j * 4 + k] * g_q[(size_t)(S0 + ss) * 4 + k];
        hs[ss][j] = cf + qf;
    }
    __syncthreads();

    for (int i = tid; i < 512; i += 256) {
        int ss = i >> 5, o = i & 31;
        float vv = cb1s[o];
        #pragma unroll
        for (int k = 0; k < 4; k++) vv += hs[ss][k] * cw1s[o * 4 + k];
        g_y1[(size_t)(S0 + ss) * 32 + o] = vv;
        ys[ss][o] = vv;
    }
    __syncthreads();

    if (tid < 32) {
        float su = 0.f, sq = 0.f;
        #pragma unroll
        for (int ss = 0; ss < 16; ss++) {
            float vv = ys[ss][tid];
            su += vv; sq += vv * vv;
        }
        g_part1[blockIdx.x * 64 + tid]      = su;
        g_part1[blockIdx.x * 64 + 32 + tid] = sq;
    }
}

// ---------------- K4: finalize BN1 stats -------------------------------------
__global__ void k_bn1(const float* __restrict__ g1, const float* __restrict__ be1, int B) {
    __shared__ float red[4][64];
    __shared__ float tot[64];
    int tid = threadIdx.x; // 256
    int qid = tid & 63, part = tid >> 6;
    int NB = B / 16;
    float sv = 0.f;
    for (int bb = part; bb < NB; bb += 4) sv += g_part1[bb * 64 + qid];
    red[part][qid] = sv;
    __syncthreads();
    if (tid < 64) tot[tid] = red[0][tid] + red[1][tid] + red[2][tid] + red[3][tid];
    __syncthreads();
    if (tid < 32) {
        float invB  = 1.f / (float)B;
        float mean  = tot[tid] * invB;
        float var   = tot[32 + tid] * invB - mean * mean;
        float scale = g1[tid] * rsqrtf(var + 1e-5f);
        g_bn1[tid]      = scale;
        g_bn1[32 + tid] = be1[tid] - mean * scale;
    }
}

// ---------------- K5: BN1-apply + relu + fc2 + BN2 partials ------------------
__global__ __launch_bounds__(256) void k_fc2(const float* __restrict__ cW2,
                                             const float* __restrict__ cb2, int B) {
    __shared__ float w2[512];
    __shared__ float b2[16];
    __shared__ float bns[64];
    __shared__ float wsum[8][32];
    int tid = threadIdx.x;
    for (int i = tid; i < 512; i += 256) w2[i] = cW2[i];
    if (tid < 16) b2[tid]  = cb2[tid];
    if (tid < 64) bns[tid] = g_bn1[tid];
    __syncthreads();

    int sidx = blockIdx.x * 256 + tid;
    float z[32];
    const float4* yp = (const float4*)(g_y1 + (size_t)sidx * 32);
    #pragma unroll
    for (int i = 0; i < 8; i++) {
        float4 u = yp[i];
        z[4 * i + 0] = fmaxf(u.x * bns[4 * i + 0] + bns[32 + 4 * i + 0], 0.f);
        z[4 * i + 1] = fmaxf(u.y * bns[4 * i + 1] + bns[32 + 4 * i + 1], 0.f);
        z[4 * i + 2] = fmaxf(u.z * bns[4 * i + 2] + bns[32 + 4 * i + 2], 0.f);
        z[4 * i + 3] = fmaxf(u.w * bns[4 * i + 3] + bns[32 + 4 * i + 3], 0.f);
    }
    float y2v[16];
    #pragma unroll
    for (int j = 0; j < 16; j++) {
        float a = b2[j];
        #pragma unroll
        for (int o = 0; o < 32; o++) a += z[o] * w2[j * 32 + o];
        y2v[j] = a;
    }
    float4* op = (float4*)(g_y2 + (size_t)sidx * 16);
    #pragma unroll
    for (int i = 0; i < 4; i++)
        op[i] = make_float4(y2v[4 * i], y2v[4 * i + 1], y2v[4 * i + 2], y2v[4 * i + 3]);

    int lane = tid & 31, w = tid >> 5;
    #pragma unroll
    for (int j = 0; j < 16; j++) {
        float su = y2v[j], sq = y2v[j] * y2v[j];
        #pragma unroll
        for (int o = 16; o; o >>= 1) {
            su += __shfl_xor_sync(0xffffffffu, su, o);
            sq += __shfl_xor_sync(0xffffffffu, sq, o);
        }
        if (lane == 0) { wsum[w][j] = su; wsum[w][16 + j] = sq; }
    }
    __syncthreads();
    if (tid < 32) {
        float sfull = 0.f;
        #pragma unroll
        for (int wi = 0; wi < 8; wi++) sfull += wsum[wi][tid];
        g_part2[blockIdx.x * 32 + tid] = sfull;
    }
}

// ---------------- K6: finalize BN2 stats -------------------------------------
__global__ void k_bn2(const float* __restrict__ g2, const float* __restrict__ be2, int B) {
    __shared__ float tot[32];
    int tid = threadIdx.x; // 32
    int NB = B / 256;
    float sv = 0.f;
    for (int bb = 0; bb < NB; bb++) sv += g_part2[bb * 32 + tid];
    tot[tid] = sv;
    __syncthreads();
    if (tid < 16) {
        float invB  = 1.f / (float)B;
        float mean  = tot[tid] * invB;
        float var   = tot[16 + tid] * invB - mean * mean;
        float scale = g2[tid] * rsqrtf(var + 1e-5f);
        g_bn2[tid]      = scale;
        g_bn2[16 + tid] = be2[tid] - mean * scale;
    }
}

// ---------------- K7: BN2-apply + relu + fc3 + relu + fc4 + sigmoid ----------
__global__ __launch_bounds__(256) void k_tail(
    const float* __restrict__ cW3, const float* __restrict__ cb3,
    const float* __restrict__ cW4, const float* __restrict__ cb4,
    float* __restrict__ out, int B)
{
    __shared__ float w3[128], b3[8], w4[8], bn[32];
    int tid = threadIdx.x;
    if (tid < 128) w3[tid] = cW3[tid];
    if (tid < 8)  { b3[tid] = cb3[tid]; w4[tid] = cW4[tid]; }
    if (tid < 32)  bn[tid] = g_bn2[tid];
    __syncthreads();

    int sidx = blockIdx.x * 256 + tid;
    float z2[16];
    const float4* yp = (const float4*)(g_y2 + (size_t)sidx * 16);
    #pragma unroll
    for (int i = 0; i < 4; i++) {
        float4 u = yp[i];
        z2[4 * i + 0] = fmaxf(u.x * bn[4 * i + 0] + bn[16 + 4 * i + 0], 0.f);
        z2[4 * i + 1] = fmaxf(u.y * bn[4 * i + 1] + bn[16 + 4 * i + 1], 0.f);
        z2[4 * i + 2] = fmaxf(u.z * bn[4 * i + 2] + bn[16 + 4 * i + 2], 0.f);
        z2[4 * i + 3] = fmaxf(u.w * bn[4 * i + 3] + bn[16 + 4 * i + 3], 0.f);
    }
    float o = cb4[0];
    #pragma unroll
    for (int j = 0; j < 8; j++) {
        float a = b3[j];
        #pragma unroll
        for (int k = 0; k < 16; k++) a += z2[k] * w3[j * 16 + k];
        o += fmaxf(a, 0.f) * w4[j];
    }
    out[sidx] = 1.f / (1.f + expf(-o));
}

// ---------------- launch ------------------------------------------------------
extern "C" void kernel_launch(void* const* d_in, const int* in_sizes, int n_in,
                              void* d_out, int out_size) {
    const float* x    = (const float*)d_in[0];
    const float* qw   = (const float*)d_in[1];
    const float* aW   = (const float*)d_in[2];
    const float* ab   = (const float*)d_in[3];
    const float* fW1  = (const float*)d_in[4];
    const float* fb1  = (const float*)d_in[5];
    const float* fW2  = (const float*)d_in[6];
    const float* fb2  = (const float*)d_in[7];
    const float* cW1  = (const float*)d_in[8];
    const float* cb1  = (const float*)d_in[9];
    const float* g1   = (const float*)d_in[10];
    const float* be1  = (const float*)d_in[11];
    const float* cW2  = (const float*)d_in[12];
    const float* cb2  = (const float*)d_in[13];
    const float* g2   = (const float*)d_in[14];
    const float* be2  = (const float*)d_in[15];
    const float* cW3  = (const float*)d_in[16];
    const float* cb3  = (const float*)d_in[17];
    const float* cW4  = (const float*)d_in[18];
    const float* cb4  = (const float*)d_in[19];

    int B = in_sizes[0] / 256;

    k_gates<<<1, 64>>>(qw);
    k_qsim<<<B, 128>>>(x, B);
    k_feat<<<B / 16, 256>>>(x, aW, ab, fW1, fb1, fW2, fb2, cW1, cb1, B);
    k_bn1<<<1, 256>>>(g1, be1, B);
    k_fc2<<<B / 256, 256>>>(cW2, cb2, B);
    k_bn2<<<1, 32>>>(g2, be2, B);
    k_tail<<<B / 256, 256>>>(cW3, cb3, cW4, cb4, (float*)d_out, B);
}

// round 3
// speedup vs baseline: 1.8528x; 1.8528x over previous
#include <cuda_runtime.h>
#include <math.h>

#define NQ 8
#define DIM 256
#define NL 6
#define MAXB 8192

typedef unsigned long long u64;

// ---------------- scratch ----------------
__device__ float  g_q[MAXB * 4];              // quantum Z expectations
__device__ float  g_y1[MAXB * 32];            // pre-BN1 activations
__device__ float  g_y2[MAXB * 16];            // pre-BN2 activations
__device__ float  g_part1[(MAXB / 16) * 64];  // per-block BN1 partial sum/sumsq
__device__ float  g_part2[(MAXB / 256) * 32]; // per-block BN2 partial sum/sumsq

__device__ __forceinline__ float2 cmul(float2 a, float2 b) {
    return make_float2(a.x * b.x - a.y * b.y, a.x * b.y + a.y * b.x);
}
__device__ __forceinline__ float2 cadd(float2 a, float2 b) {
    return make_float2(a.x + b.x, a.y + b.y);
}

// ---- packed f32x2 helpers (Blackwell FFMA2 via PTX) ----
__device__ __forceinline__ u64 fma2(u64 a, u64 b, u64 c) {
    u64 d; asm("fma.rn.f32x2 %0,%1,%2,%3;" : "=l"(d) : "l"(a), "l"(b), "l"(c)); return d;
}
__device__ __forceinline__ u64 mul2(u64 a, u64 b) {
    u64 d; asm("mul.rn.f32x2 %0,%1,%2;" : "=l"(d) : "l"(a), "l"(b)); return d;
}
__device__ __forceinline__ u64 pack2(float lo, float hi) {
    u64 d; asm("mov.b64 %0,{%1,%2};" : "=l"(d) : "f"(lo), "f"(hi)); return d;
}
__device__ __forceinline__ float2 unpack2(u64 v) {
    float2 r; asm("mov.b64 {%0,%1},%2;" : "=f"(r.x), "=f"(r.y) : "l"(v)); return r;
}
__device__ __forceinline__ u64 splat2(float v) { return pack2(v, v); }
__device__ __forceinline__ u64 swap2(u64 v) { float2 r = unpack2(v); return pack2(r.y, r.x); }
__device__ __forceinline__ u64 shflxor2(u64 v, int m) {
    return __shfl_xor_sync(0xffffffffu, v, m);
}

// ---------------- K1: quantum sim, one warp per sample ----------------------
// State of 256 complex amps: lane l holds amps [8l, 8l+8) in SoA f32x2 form:
//   xv[v] = (Re[8l+2v], Re[8l+2v+1]), yv[v] = (Im ...), v=0..3.
// Amp-index bit bp: bp<3 in-thread, bp>=3 => lane bit (bp-3).
__global__ __launch_bounds__(256) void k_qsim(const float* __restrict__ x,
                                              const float* __restrict__ qw, int B) {
    __shared__ float2 gsh[NL * NQ * 4];
    __shared__ float  sre[8][256];
    __shared__ float  sim_[8][256];

    int t = threadIdx.x;
    int w = t >> 5, l = t & 31;

    // compute combined gate matrices U = RZ*RY*RX (threads 0..47)
    if (t < NL * NQ) {
        int lay = t >> 3, q = t & 7;
        float tx = 0.5f * qw[lay * 24 + q * 3 + 0];
        float ty = 0.5f * qw[lay * 24 + q * 3 + 1];
        float tz = 0.5f * qw[lay * 24 + q * 3 + 2];
        float cx = cosf(tx), sx = sinf(tx);
        float cy = cosf(ty), sy = sinf(ty);
        float cz = cosf(tz), sz = sinf(tz);
        float2 RX0 = make_float2(cx, 0.f), RX1 = make_float2(0.f, -sx);
        float2 RX2 = make_float2(0.f, -sx), RX3 = make_float2(cx, 0.f);
        float2 RY0 = make_float2(cy, 0.f), RY1 = make_float2(-sy, 0.f);
        float2 RY2 = make_float2(sy, 0.f), RY3 = make_float2(cy, 0.f);
        float2 RZ0 = make_float2(cz, -sz), RZ3 = make_float2(cz, sz);
        float2 M0 = cadd(cmul(RY0, RX0), cmul(RY1, RX2));
        float2 M1 = cadd(cmul(RY0, RX1), cmul(RY1, RX3));
        float2 M2 = cadd(cmul(RY2, RX0), cmul(RY3, RX2));
        float2 M3 = cadd(cmul(RY2, RX1), cmul(RY3, RX3));
        gsh[t * 4 + 0] = cmul(RZ0, M0);
        gsh[t * 4 + 1] = cmul(RZ0, M1);
        gsh[t * 4 + 2] = cmul(RZ3, M2);
        gsh[t * 4 + 3] = cmul(RZ3, M3);
    }

    int b = blockIdx.x * 8 + w;

    // load 8 real amps per lane
    const float4* xp = (const float4*)(x + (size_t)b * DIM + l * 8);
    float4 v0 = xp[0], v1 = xp[1];
    u64 xv[4], yv[4];
    xv[0] = pack2(v0.x, v0.y); xv[1] = pack2(v0.z, v0.w);
    xv[2] = pack2(v1.x, v1.y); xv[3] = pack2(v1.z, v1.w);
    yv[0] = yv[1] = yv[2] = yv[3] = 0ull;

    // ||x||^2 (defer normalization)
    float nr = v0.x*v0.x + v0.y*v0.y + v0.z*v0.z + v0.w*v0.w
             + v1.x*v1.x + v1.y*v1.y + v1.z*v1.z + v1.w*v1.w;
    #pragma unroll
    for (int o = 16; o; o >>= 1) nr += __shfl_xor_sync(0xffffffffu, nr, o);

    // per-layer CNOT-block permutation (verified): new[i] = old[perm(i)]
    const int cbs[11] = {3, 5, 7, 0, 1, 2, 3, 4, 5, 6, 7};
    const int tbs[11] = {1, 3, 5, 7, 0, 1, 2, 3, 4, 5, 6};
    int rslot[8];
    #pragma unroll
    for (int jj = 0; jj < 8; jj++) {
        int p = l * 8 + jj;
        #pragma unroll
        for (int gi = 0; gi < 11; gi++)
            p ^= ((p >> cbs[gi]) & 1) << tbs[gi];
        rslot[jj] = ((p & 7) << 5) | (p >> 3);  // staging slot of source amp
    }

    __syncthreads();

    for (int lay = 0; lay < NL; lay++) {
        #pragma unroll
        for (int q = 0; q < NQ; q++) {
            const int bp = 7 - q;
            const float2* U = &gsh[(lay * 8 + q) * 4];
            float2 u0 = U[0], u1 = U[1], u2 = U[2], u3 = U[3];

            if (bp >= 3) {
                // lane-exchange gate
                int msk = 1 << (bp - 3);
                int myb = (l >> (bp - 3)) & 1;
                float2 uA = myb ? u3 : u0;
                float2 uB = myb ? u2 : u1;
                u64 uAx = splat2(uA.x), uAy = splat2(uA.y), nuAy = splat2(-uA.y);
                u64 uBx = splat2(uB.x), uBy = splat2(uB.y), nuBy = splat2(-uB.y);
                #pragma unroll
                for (int v = 0; v < 4; v++) {
                    u64 px = shflxor2(xv[v], msk);
                    u64 py = shflxor2(yv[v], msk);
                    u64 nx = fma2(uAx, xv[v], fma2(nuAy, yv[v], fma2(uBx, px, mul2(nuBy, py))));
                    u64 ny = fma2(uAx, yv[v], fma2(uAy, xv[v], fma2(uBx, py, mul2(uBy, px))));
                    xv[v] = nx; yv[v] = ny;
                }
            } else if (bp >= 1) {
                // cross-vector in-thread gate
                u64 u0x = splat2(u0.x), u0y = splat2(u0.y), nu0y = splat2(-u0.y);
                u64 u1x = splat2(u1.x), u1y = splat2(u1.y), nu1y = splat2(-u1.y);
                u64 u2x = splat2(u2.x), u2y = splat2(u2.y), nu2y = splat2(-u2.y);
                u64 u3x = splat2(u3.x), u3y = splat2(u3.y), nu3y = splat2(-u3.y);
                #pragma unroll
                for (int pr = 0; pr < 2; pr++) {
                    int a = (bp == 1) ? (pr * 2) : pr;       // bp=1:(0,1),(2,3); bp=2:(0,2),(1,3)
                    int c = (bp == 1) ? (pr * 2 + 1) : (pr + 2);
                    u64 ax = xv[a], ay = yv[a], bx = xv[c], by = yv[c];
                    xv[a] = fma2(u0x, ax, fma2(nu0y, ay, fma2(u1x, bx, mul2(nu1y, by))));
                    yv[a] = fma2(u0x, ay, fma2(u0y, ax, fma2(u1x, by, mul2(u1y, bx))));
                    xv[c] = fma2(u2x, ax, fma2(nu2y, ay, fma2(u3x, bx, mul2(nu3y, by))));
                    yv[c] = fma2(u2x, ay, fma2(u2y, ax, fma2(u3x, by, mul2(u3y, bx))));
                }
            } else {
                // within-vector gate (pairs are the two f32x2 lanes)
                u64 Ax = pack2(u0.x, u3.x), Ay = pack2(u0.y, u3.y), nAy = pack2(-u0.y, -u3.y);
                u64 Bx = pack2(u1.x, u2.x), By = pack2(u1.y, u2.y), nBy = pack2(-u1.y, -u2.y);
                #pragma unroll
                for (int v = 0; v < 4; v++) {
                    u64 xs_ = swap2(xv[v]);
                    u64 ys_ = swap2(yv[v]);
                    u64 nx = fma2(Ax, xv[v], fma2(nAy, yv[v], fma2(Bx, xs_, mul2(nBy, ys_))));
                    u64 ny = fma2(Ax, yv[v], fma2(Ay, xv[v], fma2(Bx, ys_, mul2(By, xs_))));
                    xv[v] = nx; yv[v] = ny;
                }
            }
        }
        // CNOT block: permutation through per-warp staging (amp a -> slot (a&7)*32 + a>>3)
        __syncwarp();
        #pragma unroll
        for (int v = 0; v < 4; v++) {
            float2 rx = unpack2(xv[v]), ry = unpack2(yv[v]);
            sre[w][(2 * v) * 32 + l]     = rx.x;
            sre[w][(2 * v + 1) * 32 + l] = rx.y;
            sim_[w][(2 * v) * 32 + l]     = ry.x;
            sim_[w][(2 * v + 1) * 32 + l] = ry.y;
        }
        __syncwarp();
        #pragma unroll
        for (int v = 0; v < 4; v++) {
            xv[v] = pack2(sre[w][rslot[2 * v]], sre[w][rslot[2 * v + 1]]);
            yv[v] = pack2(sim_[w][rslot[2 * v]], sim_[w][rslot[2 * v + 1]]);
        }
    }

    // probabilities; signs depend only on lane (amp>>3 == l)
    u64 pacc = mul2(xv[0], xv[0]);
    pacc = fma2(yv[0], yv[0], pacc);
    #pragma unroll
    for (int v = 1; v < 4; v++) {
        pacc = fma2(xv[v], xv[v], pacc);
        pacc = fma2(yv[v], yv[v], pacc);
    }
    float2 pp = unpack2(pacc);
    float P = pp.x + pp.y;

    float e0 = (l & 16) ? -P : P;
    float e1 = (l & 8)  ? -P : P;
    float e2 = (l & 4)  ? -P : P;
    float e3 = (l & 2)  ? -P : P;
    #pragma unroll
    for (int o = 16; o; o >>= 1) {
        e0 += __shfl_xor_sync(0xffffffffu, e0, o);
        e1 += __shfl_xor_sync(0xffffffffu, e1, o);
        e2 += __shfl_xor_sync(0xffffffffu, e2, o);
        e3 += __shfl_xor_sync(0xffffffffu, e3, o);
    }
    if (l == 0) {
        float inv = 1.f / nr;
        ((float4*)g_q)[b] = make_float4(e0 * inv, e1 * inv, e2 * inv, e3 * inv);
    }
}

// ---------------- K2: feature processor + adapter + fc1 + BN1 partials -------
__global__ __launch_bounds__(256) void k_feat(
    const float* __restrict__ x,
    const float* __restrict__ aW, const float* __restrict__ ab,
    const float* __restrict__ fW1, const float* __restrict__ fb1,
    const float* __restrict__ fW2, const float* __restrict__ fb2,
    const float* __restrict__ cW1, const float* __restrict__ cb1, int B)
{
    __shared__ float xs[16][257];
    __shared__ float ws[64][65];
    __shared__ float h1s[16][65];
    __shared__ float hs[16][4];
    __shared__ float ys[16][33];
    __shared__ float fw2s[256], cw1s[128];
    __shared__ float fb2s[4], abs_[4], aWs[16], cb1s[32];

    int tid = threadIdx.x;
    int S0 = blockIdx.x * 16;

    for (int i = tid; i < 16 * 256; i += 256) {
        int s = i >> 8, k = i & 255;
        xs[s][k] = x[(size_t)(S0 + s) * 256 + k];
    }
    fw2s[tid] = fW2[tid];
    if (tid < 128) cw1s[tid] = cW1[tid];
    if (tid < 32)  cb1s[tid] = cb1[tid];
    if (tid < 16)  aWs[tid]  = aW[tid];
    if (tid < 4) { fb2s[tid] = fb2[tid]; abs_[tid] = ab[tid]; }

    int s  = tid & 15;
    int og = tid >> 4;
    float acc0 = 0.f, acc1 = 0.f, acc2 = 0.f, acc3 = 0.f;

    for (int kc = 0; kc < 4; kc++) {
        __syncthreads();
        for (int i = tid; i < 64 * 64; i += 256) {
            int o = i >> 6, k = i & 63;
            ws[o][k] = fW1[o * 256 + kc * 64 + k];
        }
        __syncthreads();
        #pragma unroll 8
        for (int k = 0; k < 64; k++) {
            float xvv = xs[s][kc * 64 + k];
            acc0 += ws[og * 4 + 0][k] * xvv;
            acc1 += ws[og * 4 + 1][k] * xvv;
            acc2 += ws[og * 4 + 2][k] * xvv;
            acc3 += ws[og * 4 + 3][k] * xvv;
        }
    }
    h1s[s][og * 4 + 0] = fmaxf(acc0 + fb1[og * 4 + 0], 0.f);
    h1s[s][og * 4 + 1] = fmaxf(acc1 + fb1[og * 4 + 1], 0.f);
    h1s[s][og * 4 + 2] = fmaxf(acc2 + fb1[og * 4 + 2], 0.f);
    h1s[s][og * 4 + 3] = fmaxf(acc3 + fb1[og * 4 + 3], 0.f);
    __syncthreads();

    if (tid < 64) {
        int ss = tid & 15, j = tid >> 4;
        float a = fb2s[j];
        #pragma unroll 8
        for (int k = 0; k < 64; k++) a += h1s[ss][k] * fw2s[j * 64 + k];
        float cf = tanhf(a);
        float qf = abs_[j];
        #pragma unroll
        for (int k = 0; k < 4; k++) qf += aWs[j * 4 + k] * g_q[(size_t)(S0 + ss) * 4 + k];
        hs[ss][j] = cf + qf;
    }
    __syncthreads();

    for (int i = tid; i < 512; i += 256) {
        int ss = i >> 5, o = i & 31;
        float vv = cb1s[o];
        #pragma unroll
        for (int k = 0; k < 4; k++) vv += hs[ss][k] * cw1s[o * 4 + k];
        g_y1[(size_t)(S0 + ss) * 32 + o] = vv;
        ys[ss][o] = vv;
    }
    __syncthreads();

    if (tid < 32) {
        float su = 0.f, sq = 0.f;
        #pragma unroll
        for (int ss = 0; ss < 16; ss++) {
            float vv = ys[ss][tid];
            su += vv; sq += vv * vv;
        }
        g_part1[blockIdx.x * 64 + tid]      = su;
        g_part1[blockIdx.x * 64 + 32 + tid] = sq;
    }
}

// ---------------- K3: BN1 finalize (redundant per block) + relu + fc2 + BN2 partials
__global__ __launch_bounds__(256) void k_fc2(const float* __restrict__ cW2,
                                             const float* __restrict__ cb2,
                                             const float* __restrict__ g1,
                                             const float* __restrict__ be1, int B) {
    __shared__ float w2[512];
    __shared__ float b2[16];
    __shared__ float bns[64];
    __shared__ float red1[4][64];
    __shared__ float tot1[64];
    __shared__ float wsum[8][32];
    int tid = threadIdx.x;

    // BN1 stats from partials (every block does this; ~131KB from L2)
    {
        int c = tid & 63, rp = tid >> 6;
        int NB = B / 16;
        float sv = 0.f;
        for (int bb = rp; bb < NB; bb += 4) sv += g_part1[bb * 64 + c];
        red1[rp][c] = sv;
    }
    for (int i = tid; i < 512; i += 256) w2[i] = cW2[i];
    if (tid < 16) b2[tid] = cb2[tid];
    __syncthreads();
    if (tid < 64) tot1[tid] = red1[0][tid] + red1[1][tid] + red1[2][tid] + red1[3][tid];
    __syncthreads();
    if (tid < 32) {
        float invB  = 1.f / (float)B;
        float mean  = tot1[tid] * invB;
        float var   = tot1[32 + tid] * invB - mean * mean;
        float scale = g1[tid] * rsqrtf(var + 1e-5f);
        bns[tid]      = scale;
        bns[32 + tid] = be1[tid] - mean * scale;
    }
    __syncthreads();

    int sidx = blockIdx.x * 256 + tid;
    float z[32];
    const float4* yp = (const float4*)(g_y1 + (size_t)sidx * 32);
    #pragma unroll
    for (int i = 0; i < 8; i++) {
        float4 u = yp[i];
        z[4 * i + 0] = fmaxf(u.x * bns[4 * i + 0] + bns[32 + 4 * i + 0], 0.f);
        z[4 * i + 1] = fmaxf(u.y * bns[4 * i + 1] + bns[32 + 4 * i + 1], 0.f);
        z[4 * i + 2] = fmaxf(u.z * bns[4 * i + 2] + bns[32 + 4 * i + 2], 0.f);
        z[4 * i + 3] = fmaxf(u.w * bns[4 * i + 3] + bns[32 + 4 * i + 3], 0.f);
    }
    float y2v[16];
    #pragma unroll
    for (int j = 0; j < 16; j++) {
        float a = b2[j];
        #pragma unroll
        for (int o = 0; o < 32; o++) a += z[o] * w2[j * 32 + o];
        y2v[j] = a;
    }
    float4* op = (float4*)(g_y2 + (size_t)sidx * 16);
    #pragma unroll
    for (int i = 0; i < 4; i++)
        op[i] = make_float4(y2v[4 * i], y2v[4 * i + 1], y2v[4 * i + 2], y2v[4 * i + 3]);

    int lane = tid & 31, w = tid >> 5;
    #pragma unroll
    for (int j = 0; j < 16; j++) {
        float su = y2v[j], sq = y2v[j] * y2v[j];
        #pragma unroll
        for (int o = 16; o; o >>= 1) {
            su += __shfl_xor_sync(0xffffffffu, su, o);
            sq += __shfl_xor_sync(0xffffffffu, sq, o);
        }
        if (lane == 0) { wsum[w][j] = su; wsum[w][16 + j] = sq; }
    }
    __syncthreads();
    if (tid < 32) {
        float sfull = 0.f;
        #pragma unroll
        for (int wi = 0; wi < 8; wi++) sfull += wsum[wi][tid];
        g_part2[blockIdx.x * 32 + tid] = sfull;
    }
}

// ---------------- K4: BN2 finalize (redundant) + relu + fc3 + relu + fc4 + sigmoid
__global__ __launch_bounds__(256) void k_tail(
    const float* __restrict__ cW3, const float* __restrict__ cb3,
    const float* __restrict__ cW4, const float* __restrict__ cb4,
    const float* __restrict__ g2,  const float* __restrict__ be2,
    float* __restrict__ out, int B)
{
    __shared__ float w3[128], b3[8], w4[8], bn[32];
    __shared__ float red2[8][32];
    __shared__ float tot2[32];
    int tid = threadIdx.x;

    {
        int c = tid & 31, rp = tid >> 5;
        int NB2 = B / 256;
        float sv = 0.f;
        for (int bb = rp; bb < NB2; bb += 8) sv += g_part2[bb * 32 + c];
        red2[rp][c] = sv;
    }
    if (tid < 128) w3[tid] = cW3[tid];
    if (tid < 8)  { b3[tid] = cb3[tid]; w4[tid] = cW4[tid]; }
    __syncthreads();
    if (tid < 32) {
        float tt = 0.f;
        #pragma unroll
        for (int rp = 0; rp < 8; rp++) tt += red2[rp][tid];
        tot2[tid] = tt;
    }
    __syncthreads();
    if (tid < 16) {
        float invB  = 1.f / (float)B;
        float mean  = tot2[tid] * invB;
        float var   = tot2[16 + tid] * invB - mean * mean;
        float scale = g2[tid] * rsqrtf(var + 1e-5f);
        bn[tid]      = scale;
        bn[16 + tid] = be2[tid] - mean * scale;
    }
    __syncthreads();

    int sidx = blockIdx.x * 256 + tid;
    float z2[16];
    const float4* yp = (const float4*)(g_y2 + (size_t)sidx * 16);
    #pragma unroll
    for (int i = 0; i < 4; i++) {
        float4 u = yp[i];
        z2[4 * i + 0] = fmaxf(u.x * bn[4 * i + 0] + bn[16 + 4 * i + 0], 0.f);
        z2[4 * i + 1] = fmaxf(u.y * bn[4 * i + 1] + bn[16 + 4 * i + 1], 0.f);
        z2[4 * i + 2] = fmaxf(u.z * bn[4 * i + 2] + bn[16 + 4 * i + 2], 0.f);
        z2[4 * i + 3] = fmaxf(u.w * bn[4 * i + 3] + bn[16 + 4 * i + 3], 0.f);
    }
    float o = cb4[0];
    #pragma unroll
    for (int j = 0; j < 8; j++) {
        float a = b3[j];
        #pragma unroll
        for (int k = 0; k < 16; k++) a += z2[k] * w3[j * 16 + k];
        o += fmaxf(a, 0.f) * w4[j];
    }
    out[sidx] = 1.f / (1.f + expf(-o));
}

// ---------------- launch ------------------------------------------------------
extern "C" void kernel_launch(void* const* d_in, const int* in_sizes, int n_in,
                              void* d_out, int out_size) {
    const float* x    = (const float*)d_in[0];
    const float* qw   = (const float*)d_in[1];
    const float* aW   = (const float*)d_in[2];
    const float* ab   = (const float*)d_in[3];
    const float* fW1  = (const float*)d_in[4];
    const float* fb1  = (const float*)d_in[5];
    const float* fW2  = (const float*)d_in[6];
    const float* fb2  = (const float*)d_in[7];
    const float* cW1  = (const float*)d_in[8];
    const float* cb1  = (const float*)d_in[9];
    const float* g1   = (const float*)d_in[10];
    const float* be1  = (const float*)d_in[11];
    const float* cW2  = (const float*)d_in[12];
    const float* cb2  = (const float*)d_in[13];
    const float* g2   = (const float*)d_in[14];
    const float* be2  = (const float*)d_in[15];
    const float* cW3  = (const float*)d_in[16];
    const float* cb3  = (const float*)d_in[17];
    const float* cW4  = (const float*)d_in[18];
    const float* cb4  = (const float*)d_in[19];

    int B = in_sizes[0] / 256;

    k_qsim<<<B / 8, 256>>>(x, qw, B);
    k_feat<<<B / 16, 256>>>(x, aW, ab, fW1, fb1, fW2, fb2, cW1, cb1, B);
    k_fc2<<<B / 256, 256>>>(cW2, cb2, g1, be1, B);
    k_tail<<<B / 256, 256>>>(cW3, cb3, cW4, cb4, g2, be2, (float*)d_out, B);
}

// round 4
// speedup vs baseline: 2.1400x; 1.1550x over previous
#include <cuda_runtime.h>
#include <math.h>

#define NQ 8
#define DIM 256
#define NL 6
#define MAXB 8192

typedef unsigned long long u64;

// ---------------- scratch ----------------
__device__ float4 g_q4[MAXB];                 // quantum Z expectations (vec4)
__device__ float  g_y1[MAXB * 32];            // pre-BN1 activations
__device__ float  g_part1[(MAXB / 64) * 64];  // per-block BN1 partial sum/sumsq
__device__ float  g_part2[(MAXB / 256) * 32]; // per-block BN2 partial sum/sumsq
__device__ unsigned g_arrive;                 // global barrier counters (self-reset)
__device__ unsigned g_depart;

__device__ __forceinline__ float2 cmul(float2 a, float2 b) {
    return make_float2(a.x * b.x - a.y * b.y, a.x * b.y + a.y * b.x);
}
__device__ __forceinline__ float2 cadd(float2 a, float2 b) {
    return make_float2(a.x + b.x, a.y + b.y);
}

// ---- packed f32x2 helpers (Blackwell FFMA2 via PTX) ----
__device__ __forceinline__ u64 fma2(u64 a, u64 b, u64 c) {
    u64 d; asm("fma.rn.f32x2 %0,%1,%2,%3;" : "=l"(d) : "l"(a), "l"(b), "l"(c)); return d;
}
__device__ __forceinline__ u64 mul2(u64 a, u64 b) {
    u64 d; asm("mul.rn.f32x2 %0,%1,%2;" : "=l"(d) : "l"(a), "l"(b)); return d;
}
__device__ __forceinline__ u64 pack2(float lo, float hi) {
    u64 d; asm("mov.b64 %0,{%1,%2};" : "=l"(d) : "f"(lo), "f"(hi)); return d;
}
__device__ __forceinline__ float2 unpack2(u64 v) {
    float2 r; asm("mov.b64 {%0,%1},%2;" : "=f"(r.x), "=f"(r.y) : "l"(v)); return r;
}
__device__ __forceinline__ u64 splat2(float v) { return pack2(v, v); }
__device__ __forceinline__ u64 swap2(u64 v) { float2 r = unpack2(v); return pack2(r.y, r.x); }
__device__ __forceinline__ u64 shflxor2(u64 v, int m) {
    return __shfl_xor_sync(0xffffffffu, v, m);
}

// ---------------- K1: quantum sim, one warp per sample (verified R3) ---------
__global__ __launch_bounds__(256) void k_qsim(const float* __restrict__ x,
                                              const float* __restrict__ qw, int B) {
    __shared__ float2 gsh[NL * NQ * 4];
    __shared__ float  sre[8][256];
    __shared__ float  sim_[8][256];

    int t = threadIdx.x;
    int w = t >> 5, l = t & 31;

    if (t < NL * NQ) {
        int lay = t >> 3, q = t & 7;
        float tx = 0.5f * qw[lay * 24 + q * 3 + 0];
        float ty = 0.5f * qw[lay * 24 + q * 3 + 1];
        float tz = 0.5f * qw[lay * 24 + q * 3 + 2];
        float cx = cosf(tx), sx = sinf(tx);
        float cy = cosf(ty), sy = sinf(ty);
        float cz = cosf(tz), sz = sinf(tz);
        float2 RX0 = make_float2(cx, 0.f), RX1 = make_float2(0.f, -sx);
        float2 RX2 = make_float2(0.f, -sx), RX3 = make_float2(cx, 0.f);
        float2 RY0 = make_float2(cy, 0.f), RY1 = make_float2(-sy, 0.f);
        float2 RY2 = make_float2(sy, 0.f), RY3 = make_float2(cy, 0.f);
        float2 RZ0 = make_float2(cz, -sz), RZ3 = make_float2(cz, sz);
        float2 M0 = cadd(cmul(RY0, RX0), cmul(RY1, RX2));
        float2 M1 = cadd(cmul(RY0, RX1), cmul(RY1, RX3));
        float2 M2 = cadd(cmul(RY2, RX0), cmul(RY3, RX2));
        float2 M3 = cadd(cmul(RY2, RX1), cmul(RY3, RX3));
        gsh[t * 4 + 0] = cmul(RZ0, M0);
        gsh[t * 4 + 1] = cmul(RZ0, M1);
        gsh[t * 4 + 2] = cmul(RZ3, M2);
        gsh[t * 4 + 3] = cmul(RZ3, M3);
    }

    int b = blockIdx.x * 8 + w;

    const float4* xp = (const float4*)(x + (size_t)b * DIM + l * 8);
    float4 v0 = xp[0], v1 = xp[1];
    u64 xv[4], yv[4];
    xv[0] = pack2(v0.x, v0.y); xv[1] = pack2(v0.z, v0.w);
    xv[2] = pack2(v1.x, v1.y); xv[3] = pack2(v1.z, v1.w);
    yv[0] = yv[1] = yv[2] = yv[3] = 0ull;

    float nr = v0.x*v0.x + v0.y*v0.y + v0.z*v0.z + v0.w*v0.w
             + v1.x*v1.x + v1.y*v1.y + v1.z*v1.z + v1.w*v1.w;
    #pragma unroll
    for (int o = 16; o; o >>= 1) nr += __shfl_xor_sync(0xffffffffu, nr, o);

    const int cbs[11] = {3, 5, 7, 0, 1, 2, 3, 4, 5, 6, 7};
    const int tbs[11] = {1, 3, 5, 7, 0, 1, 2, 3, 4, 5, 6};
    int rslot[8];
    #pragma unroll
    for (int jj = 0; jj < 8; jj++) {
        int p = l * 8 + jj;
        #pragma unroll
        for (int gi = 0; gi < 11; gi++)
            p ^= ((p >> cbs[gi]) & 1) << tbs[gi];
        rslot[jj] = ((p & 7) << 5) | (p >> 3);
    }

    __syncthreads();

    for (int lay = 0; lay < NL; lay++) {
        #pragma unroll
        for (int q = 0; q < NQ; q++) {
            const int bp = 7 - q;
            const float2* U = &gsh[(lay * 8 + q) * 4];
            float2 u0 = U[0], u1 = U[1], u2 = U[2], u3 = U[3];

            if (bp >= 3) {
                int msk = 1 << (bp - 3);
                int myb = (l >> (bp - 3)) & 1;
                float2 uA = myb ? u3 : u0;
                float2 uB = myb ? u2 : u1;
                u64 uAx = splat2(uA.x), uAy = splat2(uA.y), nuAy = splat2(-uA.y);
                u64 uBx = splat2(uB.x), uBy = splat2(uB.y), nuBy = splat2(-uB.y);
                #pragma unroll
                for (int v = 0; v < 4; v++) {
                    u64 px = shflxor2(xv[v], msk);
                    u64 py = shflxor2(yv[v], msk);
                    u64 nx = fma2(uAx, xv[v], fma2(nuAy, yv[v], fma2(uBx, px, mul2(nuBy, py))));
                    u64 ny = fma2(uAx, yv[v], fma2(uAy, xv[v], fma2(uBx, py, mul2(uBy, px))));
                    xv[v] = nx; yv[v] = ny;
                }
            } else if (bp >= 1) {
                u64 u0x = splat2(u0.x), u0y = splat2(u0.y), nu0y = splat2(-u0.y);
                u64 u1x = splat2(u1.x), u1y = splat2(u1.y), nu1y = splat2(-u1.y);
                u64 u2x = splat2(u2.x), u2y = splat2(u2.y), nu2y = splat2(-u2.y);
                u64 u3x = splat2(u3.x), u3y = splat2(u3.y), nu3y = splat2(-u3.y);
                #pragma unroll
                for (int pr = 0; pr < 2; pr++) {
                    int a = (bp == 1) ? (pr * 2) : pr;
                    int c = (bp == 1) ? (pr * 2 + 1) : (pr + 2);
                    u64 ax = xv[a], ay = yv[a], bx = xv[c], by = yv[c];
                    xv[a] = fma2(u0x, ax, fma2(nu0y, ay, fma2(u1x, bx, mul2(nu1y, by))));
                    yv[a] = fma2(u0x, ay, fma2(u0y, ax, fma2(u1x, by, mul2(u1y, bx))));
                    xv[c] = fma2(u2x, ax, fma2(nu2y, ay, fma2(u3x, bx, mul2(nu3y, by))));
                    yv[c] = fma2(u2x, ay, fma2(u2y, ax, fma2(u3x, by, mul2(u3y, bx))));
                }
            } else {
                u64 Ax = pack2(u0.x, u3.x), Ay = pack2(u0.y, u3.y), nAy = pack2(-u0.y, -u3.y);
                u64 Bx = pack2(u1.x, u2.x), By = pack2(u1.y, u2.y), nBy = pack2(-u1.y, -u2.y);
                #pragma unroll
                for (int v = 0; v < 4; v++) {
                    u64 xs_ = swap2(xv[v]);
                    u64 ys_ = swap2(yv[v]);
                    u64 nx = fma2(Ax, xv[v], fma2(nAy, yv[v], fma2(Bx, xs_, mul2(nBy, ys_))));
                    u64 ny = fma2(Ax, yv[v], fma2(Ay, xv[v], fma2(Bx, ys_, mul2(By, xs_))));
                    xv[v] = nx; yv[v] = ny;
                }
            }
        }
        __syncwarp();
        #pragma unroll
        for (int v = 0; v < 4; v++) {
            float2 rx = unpack2(xv[v]), ry = unpack2(yv[v]);
            sre[w][(2 * v) * 32 + l]     = rx.x;
            sre[w][(2 * v + 1) * 32 + l] = rx.y;
            sim_[w][(2 * v) * 32 + l]     = ry.x;
            sim_[w][(2 * v + 1) * 32 + l] = ry.y;
        }
        __syncwarp();
        #pragma unroll
        for (int v = 0; v < 4; v++) {
            xv[v] = pack2(sre[w][rslot[2 * v]], sre[w][rslot[2 * v + 1]]);
            yv[v] = pack2(sim_[w][rslot[2 * v]], sim_[w][rslot[2 * v + 1]]);
        }
    }

    u64 pacc = mul2(xv[0], xv[0]);
    pacc = fma2(yv[0], yv[0], pacc);
    #pragma unroll
    for (int v = 1; v < 4; v++) {
        pacc = fma2(xv[v], xv[v], pacc);
        pacc = fma2(yv[v], yv[v], pacc);
    }
    float2 pp = unpack2(pacc);
    float P = pp.x + pp.y;

    float e0 = (l & 16) ? -P : P;
    float e1 = (l & 8)  ? -P : P;
    float e2 = (l & 4)  ? -P : P;
    float e3 = (l & 2)  ? -P : P;
    #pragma unroll
    for (int o = 16; o; o >>= 1) {
        e0 += __shfl_xor_sync(0xffffffffu, e0, o);
        e1 += __shfl_xor_sync(0xffffffffu, e1, o);
        e2 += __shfl_xor_sync(0xffffffffu, e2, o);
        e3 += __shfl_xor_sync(0xffffffffu, e3, o);
    }
    if (l == 0) {
        float inv = 1.f / nr;
        g_q4[b] = make_float4(e0 * inv, e1 * inv, e2 * inv, e3 * inv);
    }
}

// ---------------- K2: feature processor + adapter + fc1 + BN1 partials -------
// 64 samples per block, 256 threads, dynamic smem with aliased regions.
// Warp w computes outputs [8w, 8w+8) for all 64 samples (lane s and s+32),
// k packed pairwise into f32x2.
#define FEAT_SMEM (64*260*4 + 64*68*4 + 2048)

__global__ __launch_bounds__(256, 2) void k_feat(
    const float* __restrict__ x,
    const float* __restrict__ aW, const float* __restrict__ ab,
    const float* __restrict__ fW1, const float* __restrict__ fb1,
    const float* __restrict__ fW2, const float* __restrict__ fb2,
    const float* __restrict__ cW1, const float* __restrict__ cb1, int B)
{
    extern __shared__ __align__(16) char sm[];
    float (*xs)[260] = (float(*)[260])sm;                 // 66560 B (GEMM phase)
    float (*ws)[68]  = (float(*)[68])(sm + 66560);        // 17408 B
    float *cst       = (float*)(sm + 83968);              // 2016 B consts
    float *fw2s = cst;            // 256
    float *cw1s = cst + 256;      // 128
    float *fb1s = cst + 384;      // 64
    float *cb1s = cst + 448;      // 32
    float *fb2s = cst + 480;      // 4
    float *abs_ = cst + 484;      // 4
    float *aWs  = cst + 488;      // 16
    // aliased into xs region (only used after GEMM, post-sync):
    float (*h1s)[68] = (float(*)[68])sm;                  // 17408 B
    float (*hs)[8]   = (float(*)[8])(sm + 20480);         // 2048 B
    float (*ys)[33]  = (float(*)[33])(sm + 24576);        // 8448 B

    int tid = threadIdx.x;
    int S0 = blockIdx.x * 64;
    int w = tid >> 5, l = tid & 31;

    // load consts
    fw2s[tid] = fW2[tid];
    if (tid < 128) cw1s[tid] = cW1[tid];
    if (tid < 64)  fb1s[tid] = fb1[tid];
    if (tid < 32)  cb1s[tid] = cb1[tid];
    if (tid < 16)  aWs[tid]  = aW[tid];
    if (tid < 4) { fb2s[tid] = fb2[tid]; abs_[tid] = ab[tid]; }

    // load x tile: 64 samples x 256 (float4, coalesced)
    for (int i = tid; i < 64 * 64; i += 256) {
        int s = i >> 6, q = i & 63;
        ((float4*)&xs[s][0])[q] = ((const float4*)(x + (size_t)(S0 + s) * 256))[q];
    }

    // main GEMM: acc[sg][j] packs (even-k sum, odd-k sum)
    u64 acc[2][8];
    #pragma unroll
    for (int sg = 0; sg < 2; sg++)
        #pragma unroll
        for (int j = 0; j < 8; j++) acc[sg][j] = 0ull;

    for (int kc = 0; kc < 4; kc++) {
        __syncthreads();
        for (int i = tid; i < 64 * 16; i += 256) {
            int o = i >> 4, q = i & 15;
            ((float4*)&ws[o][0])[q] = ((const float4*)(fW1 + o * 256 + kc * 64))[q];
        }
        __syncthreads();
        const float4* xr0 = (const float4*)&xs[l][kc * 64];
        const float4* xr1 = (const float4*)&xs[l + 32][kc * 64];
        #pragma unroll
        for (int q = 0; q < 16; q++) {
            float4 a4 = xr0[q], b4 = xr1[q];
            u64 x0lo = pack2(a4.x, a4.y), x0hi = pack2(a4.z, a4.w);
            u64 x1lo = pack2(b4.x, b4.y), x1hi = pack2(b4.z, b4.w);
            #pragma unroll
            for (int j = 0; j < 8; j++) {
                float4 w4 = ((const float4*)&ws[w * 8 + j][0])[q];
                u64 wlo = pack2(w4.x, w4.y), whi = pack2(w4.z, w4.w);
                acc[0][j] = fma2(wlo, x0lo, acc[0][j]);
                acc[0][j] = fma2(whi, x0hi, acc[0][j]);
                acc[1][j] = fma2(wlo, x1lo, acc[1][j]);
                acc[1][j] = fma2(whi, x1hi, acc[1][j]);
            }
        }
    }
    __syncthreads();   // all warps done reading xs/ws before aliasing

    #pragma unroll
    for (int sg = 0; sg < 2; sg++) {
        int s = l + 32 * sg;
        #pragma unroll
        for (int j = 0; j < 8; j++) {
            float2 r = unpack2(acc[sg][j]);
            h1s[s][w * 8 + j] = fmaxf(r.x + r.y + fb1s[w * 8 + j], 0.f);
        }
    }
    __syncthreads();

    // head: tanh(fW2 @ h1 + fb2) + adapter(q)
    {
        int s = tid & 63, j = tid >> 6;   // j in 0..3
        float a = fb2s[j];
        const float4* hp = (const float4*)&h1s[s][0];
        const float4* wp = (const float4*)&fw2s[j * 64];
        #pragma unroll
        for (int q = 0; q < 16; q++) {
            float4 h = hp[q], wv = wp[q];
            a += h.x * wv.x + h.y * wv.y + h.z * wv.z + h.w * wv.w;
        }
        float cf = tanhf(a);
        float4 qv = g_q4[S0 + s];
        float qf = abs_[j] + aWs[j * 4 + 0] * qv.x + aWs[j * 4 + 1] * qv.y
                           + aWs[j * 4 + 2] * qv.z + aWs[j * 4 + 3] * qv.w;
        hs[s][j] = cf + qf;
    }
    __syncthreads();

    // cW1: 64 samples x 32 outputs
    for (int i = tid; i < 64 * 32; i += 256) {
        int s = i >> 5, o = i & 31;
        float vv = cb1s[o];
        #pragma unroll
        for (int k = 0; k < 4; k++) vv += hs[s][k] * cw1s[o * 4 + k];
        g_y1[(size_t)(S0 + s) * 32 + o] = vv;
        ys[s][o] = vv;
    }
    __syncthreads();

    if (tid < 32) {
        float su = 0.f, sq = 0.f;
        #pragma unroll
        for (int s = 0; s < 64; s++) {
            float vv = ys[s][tid];
            su += vv; sq += vv * vv;
        }
        g_part1[blockIdx.x * 64 + tid]      = su;
        g_part1[blockIdx.x * 64 + 32 + tid] = sq;
    }
}

// ---------------- K3: BN1 finalize + fc2 + [global barrier] + BN2 + tail -----
__global__ __launch_bounds__(256) void k_fc2tail(
    const float* __restrict__ cW2, const float* __restrict__ cb2,
    const float* __restrict__ g1,  const float* __restrict__ be1,
    const float* __restrict__ cW3, const float* __restrict__ cb3,
    const float* __restrict__ cW4, const float* __restrict__ cb4,
    const float* __restrict__ g2,  const float* __restrict__ be2,
    float* __restrict__ out, int B)
{
    __shared__ float w2s[512], b2s[16], bns[64];
    __shared__ float red1[4][64], tot1[64];
    __shared__ float wsum[8][32];
    __shared__ float w3s[128], b3s[8], w4s[8], bn2[32], tot2[32];
    int tid = threadIdx.x;

    // BN1 finalize from feat partials
    {
        int c = tid & 63, rp = tid >> 6;
        int NB = B / 64;
        float sv = 0.f;
        for (int bb = rp; bb < NB; bb += 4) sv += g_part1[bb * 64 + c];
        red1[rp][c] = sv;
    }
    for (int i = tid; i < 512; i += 256) w2s[i] = cW2[i];
    if (tid < 128) w3s[tid] = cW3[tid];
    if (tid < 16)  b2s[tid] = cb2[tid];
    if (tid < 8) { b3s[tid] = cb3[tid]; w4s[tid] = cW4[tid]; }
    __syncthreads();
    if (tid < 64) tot1[tid] = red1[0][tid] + red1[1][tid] + red1[2][tid] + red1[3][tid];
    __syncthreads();
    if (tid < 32) {
        float invB  = 1.f / (float)B;
        float mean  = tot1[tid] * invB;
        float var   = tot1[32 + tid] * invB - mean * mean;
        float scale = g1[tid] * rsqrtf(var + 1e-5f);
        bns[tid]      = scale;
        bns[32 + tid] = be1[tid] - mean * scale;
    }
    __syncthreads();

    int sidx = blockIdx.x * 256 + tid;
    float z[32];
    const float4* yp = (const float4*)(g_y1 + (size_t)sidx * 32);
    #pragma unroll
    for (int i = 0; i < 8; i++) {
        float4 u = yp[i];
        z[4 * i + 0] = fmaxf(u.x * bns[4 * i + 0] + bns[32 + 4 * i + 0], 0.f);
        z[4 * i + 1] = fmaxf(u.y * bns[4 * i + 1] + bns[32 + 4 * i + 1], 0.f);
        z[4 * i + 2] = fmaxf(u.z * bns[4 * i + 2] + bns[32 + 4 * i + 2], 0.f);
        z[4 * i + 3] = fmaxf(u.w * bns[4 * i + 3] + bns[32 + 4 * i + 3], 0.f);
    }
    float y2v[16];
    #pragma unroll
    for (int j = 0; j < 16; j++) {
        float a = b2s[j];
        #pragma unroll
        for (int o = 0; o < 32; o++) a += z[o] * w2s[j * 32 + o];
        y2v[j] = a;
    }

    // BN2 partials (y2 stays in registers)
    int lane = tid & 31, wp2 = tid >> 5;
    #pragma unroll
    for (int j = 0; j < 16; j++) {
        float su = y2v[j], sq = y2v[j] * y2v[j];
        #pragma unroll
        for (int o = 16; o; o >>= 1) {
            su += __shfl_xor_sync(0xffffffffu, su, o);
            sq += __shfl_xor_sync(0xffffffffu, sq, o);
        }
        if (lane == 0) { wsum[wp2][j] = su; wsum[wp2][16 + j] = sq; }
    }
    __syncthreads();
    if (tid < 32) {
        float sfull = 0.f;
        #pragma unroll
        for (int wi = 0; wi < 8; wi++) sfull += wsum[wi][tid];
        g_part2[blockIdx.x * 32 + tid] = sfull;
    }
    __syncthreads();

    // ---- device-wide barrier (all gridDim.x blocks resident; self-resetting)
    if (tid == 0) {
        __threadfence();
        atomicAdd(&g_arrive, 1u);
        while (atomicAdd(&g_arrive, 0u) < gridDim.x) { }
        unsigned d = atomicAdd(&g_depart, 1u) + 1u;
        if (d == gridDim.x) {
            atomicExch(&g_arrive, 0u);
            atomicExch(&g_depart, 0u);
        }
    }
    __syncthreads();

    // BN2 finalize
    if (tid < 32) {
        float sv = 0.f;
        int NB2 = B / 256;
        for (int bb = 0; bb < NB2; bb++) sv += __ldcg(&g_part2[bb * 32 + tid]);
        tot2[tid] = sv;
    }
    __syncthreads();
    if (tid < 16) {
        float invB  = 1.f / (float)B;
        float mean  = tot2[tid] * invB;
        float var   = tot2[16 + tid] * invB - mean * mean;
        float scale = g2[tid] * rsqrtf(var + 1e-5f);
        bn2[tid]      = scale;
        bn2[16 + tid] = be2[tid] - mean * scale;
    }
    __syncthreads();

    // tail: BN2 + relu + fc3 + relu + fc4 + sigmoid (from registers)
    float z2[16];
    #pragma unroll
    for (int j = 0; j < 16; j++)
        z2[j] = fmaxf(y2v[j] * bn2[j] + bn2[16 + j], 0.f);
    float o = cb4[0];
    #pragma unroll
    for (int j = 0; j < 8; j++) {
        float a = b3s[j];
        #pragma unroll
        for (int k = 0; k < 16; k++) a += z2[k] * w3s[j * 16 + k];
        o += fmaxf(a, 0.f) * w4s[j];
    }
    out[sidx] = 1.f / (1.f + expf(-o));
}

// ---------------- launch ------------------------------------------------------
extern "C" void kernel_launch(void* const* d_in, const int* in_sizes, int n_in,
                              void* d_out, int out_size) {
    const float* x    = (const float*)d_in[0];
    const float* qw   = (const float*)d_in[1];
    const float* aW   = (const float*)d_in[2];
    const float* ab   = (const float*)d_in[3];
    const float* fW1  = (const float*)d_in[4];
    const float* fb1  = (const float*)d_in[5];
    const float* fW2  = (const float*)d_in[6];
    const float* fb2  = (const float*)d_in[7];
    const float* cW1  = (const float*)d_in[8];
    const float* cb1  = (const float*)d_in[9];
    const float* g1   = (const float*)d_in[10];
    const float* be1  = (const float*)d_in[11];
    const float* cW2  = (const float*)d_in[12];
    const float* cb2  = (const float*)d_in[13];
    const float* g2   = (const float*)d_in[14];
    const float* be2  = (const float*)d_in[15];
    const float* cW3  = (const float*)d_in[16];
    const float* cb3  = (const float*)d_in[17];
    const float* cW4  = (const float*)d_in[18];
    const float* cb4  = (const float*)d_in[19];

    int B = in_sizes[0] / 256;

    static_assert(FEAT_SMEM <= 112 * 1024, "smem budget");
    cudaFuncSetAttribute(k_feat, cudaFuncAttributeMaxDynamicSharedMemorySize, FEAT_SMEM);

    k_qsim<<<B / 8, 256>>>(x, qw, B);
    k_feat<<<B / 64, 256, FEAT_SMEM>>>(x, aW, ab, fW1, fb1, fW2, fb2, cW1, cb1, B);
    k_fc2tail<<<B / 256, 256>>>(cW2, cb2, g1, be1, cW3, cb3, cW4, cb4, g2, be2,
                                (float*)d_out, B);
}

// round 6
// speedup vs baseline: 2.1411x; 1.0005x over previous
#include <cuda_runtime.h>
#include <math.h>

#define NQ 8
#define DIM 256
#define NL 6
#define MAXB 8192

typedef unsigned long long u64;

// ---------------- scratch ----------------
__device__ float4 g_q4[MAXB];                 // quantum Z expectations (vec4)
__device__ float  g_y1[MAXB * 32];            // pre-BN1 activations
__device__ float  g_part1[(MAXB / 64) * 64];  // per-block BN1 partial sum/sumsq
__device__ float  g_part2[(MAXB / 256) * 32]; // per-block BN2 partial sum/sumsq
__device__ unsigned g_arrive;                 // global barrier counters (self-reset)
__device__ unsigned g_depart;

__device__ __forceinline__ float2 cmul(float2 a, float2 b) {
    return make_float2(a.x * b.x - a.y * b.y, a.x * b.y + a.y * b.x);
}
__device__ __forceinline__ float2 cadd(float2 a, float2 b) {
    return make_float2(a.x + b.x, a.y + b.y);
}

// ---- packed f32x2 helpers (Blackwell FFMA2 via PTX) ----
__device__ __forceinline__ u64 fma2(u64 a, u64 b, u64 c) {
    u64 d; asm("fma.rn.f32x2 %0,%1,%2,%3;" : "=l"(d) : "l"(a), "l"(b), "l"(c)); return d;
}
__device__ __forceinline__ u64 mul2(u64 a, u64 b) {
    u64 d; asm("mul.rn.f32x2 %0,%1,%2;" : "=l"(d) : "l"(a), "l"(b)); return d;
}
__device__ __forceinline__ u64 pack2(float lo, float hi) {
    u64 d; asm("mov.b64 %0,{%1,%2};" : "=l"(d) : "f"(lo), "f"(hi)); return d;
}
__device__ __forceinline__ float2 unpack2(u64 v) {
    float2 r; asm("mov.b64 {%0,%1},%2;" : "=f"(r.x), "=f"(r.y) : "l"(v)); return r;
}
__device__ __forceinline__ u64 splat2(float v) { return pack2(v, v); }
__device__ __forceinline__ u64 swap2(u64 v) { float2 r = unpack2(v); return pack2(r.y, r.x); }
__device__ __forceinline__ u64 shflxor2(u64 v, int m) {
    return __shfl_xor_sync(0xffffffffu, v, m);
}

// ---------------- K1: quantum sim, one warp per sample (verified R3) ---------
__global__ __launch_bounds__(256) void k_qsim(const float* __restrict__ x,
                                              const float* __restrict__ qw, int B) {
    __shared__ float2 gsh[NL * NQ * 4];
    __shared__ float  sre[8][256];
    __shared__ float  sim_[8][256];

    int t = threadIdx.x;
    int w = t >> 5, l = t & 31;

    if (t < NL * NQ) {
        int lay = t >> 3, q = t & 7;
        float tx = 0.5f * qw[lay * 24 + q * 3 + 0];
        float ty = 0.5f * qw[lay * 24 + q * 3 + 1];
        float tz = 0.5f * qw[lay * 24 + q * 3 + 2];
        float cx = cosf(tx), sx = sinf(tx);
        float cy = cosf(ty), sy = sinf(ty);
        float cz = cosf(tz), sz = sinf(tz);
        float2 RX0 = make_float2(cx, 0.f), RX1 = make_float2(0.f, -sx);
        float2 RX2 = make_float2(0.f, -sx), RX3 = make_float2(cx, 0.f);
        float2 RY0 = make_float2(cy, 0.f), RY1 = make_float2(-sy, 0.f);
        float2 RY2 = make_float2(sy, 0.f), RY3 = make_float2(cy, 0.f);
        float2 RZ0 = make_float2(cz, -sz), RZ3 = make_float2(cz, sz);
        float2 M0 = cadd(cmul(RY0, RX0), cmul(RY1, RX2));
        float2 M1 = cadd(cmul(RY0, RX1), cmul(RY1, RX3));
        float2 M2 = cadd(cmul(RY2, RX0), cmul(RY3, RX2));
        float2 M3 = cadd(cmul(RY2, RX1), cmul(RY3, RX3));
        gsh[t * 4 + 0] = cmul(RZ0, M0);
        gsh[t * 4 + 1] = cmul(RZ0, M1);
        gsh[t * 4 + 2] = cmul(RZ3, M2);
        gsh[t * 4 + 3] = cmul(RZ3, M3);
    }

    int b = blockIdx.x * 8 + w;

    const float4* xp = (const float4*)(x + (size_t)b * DIM + l * 8);
    float4 v0 = xp[0], v1 = xp[1];
    u64 xv[4], yv[4];
    xv[0] = pack2(v0.x, v0.y); xv[1] = pack2(v0.z, v0.w);
    xv[2] = pack2(v1.x, v1.y); xv[3] = pack2(v1.z, v1.w);
    yv[0] = yv[1] = yv[2] = yv[3] = 0ull;

    float nr = v0.x*v0.x + v0.y*v0.y + v0.z*v0.z + v0.w*v0.w
             + v1.x*v1.x + v1.y*v1.y + v1.z*v1.z + v1.w*v1.w;
    #pragma unroll
    for (int o = 16; o; o >>= 1) nr += __shfl_xor_sync(0xffffffffu, nr, o);

    const int cbs[11] = {3, 5, 7, 0, 1, 2, 3, 4, 5, 6, 7};
    const int tbs[11] = {1, 3, 5, 7, 0, 1, 2, 3, 4, 5, 6};
    int rslot[8];
    #pragma unroll
    for (int jj = 0; jj < 8; jj++) {
        int p = l * 8 + jj;
        #pragma unroll
        for (int gi = 0; gi < 11; gi++)
            p ^= ((p >> cbs[gi]) & 1) << tbs[gi];
        rslot[jj] = ((p & 7) << 5) | (p >> 3);
    }

    __syncthreads();

    for (int lay = 0; lay < NL; lay++) {
        #pragma unroll
        for (int q = 0; q < NQ; q++) {
            const int bp = 7 - q;
            const float2* U = &gsh[(lay * 8 + q) * 4];
            float2 u0 = U[0], u1 = U[1], u2 = U[2], u3 = U[3];

            if (bp >= 3) {
                int msk = 1 << (bp - 3);
                int myb = (l >> (bp - 3)) & 1;
                float2 uA = myb ? u3 : u0;
                float2 uB = myb ? u2 : u1;
                u64 uAx = splat2(uA.x), uAy = splat2(uA.y), nuAy = splat2(-uA.y);
                u64 uBx = splat2(uB.x), uBy = splat2(uB.y), nuBy = splat2(-uB.y);
                #pragma unroll
                for (int v = 0; v < 4; v++) {
                    u64 px = shflxor2(xv[v], msk);
                    u64 py = shflxor2(yv[v], msk);
                    u64 nx = fma2(uAx, xv[v], fma2(nuAy, yv[v], fma2(uBx, px, mul2(nuBy, py))));
                    u64 ny = fma2(uAx, yv[v], fma2(uAy, xv[v], fma2(uBx, py, mul2(uBy, px))));
                    xv[v] = nx; yv[v] = ny;
                }
            } else if (bp >= 1) {
                u64 u0x = splat2(u0.x), u0y = splat2(u0.y), nu0y = splat2(-u0.y);
                u64 u1x = splat2(u1.x), u1y = splat2(u1.y), nu1y = splat2(-u1.y);
                u64 u2x = splat2(u2.x), u2y = splat2(u2.y), nu2y = splat2(-u2.y);
                u64 u3x = splat2(u3.x), u3y = splat2(u3.y), nu3y = splat2(-u3.y);
                #pragma unroll
                for (int pr = 0; pr < 2; pr++) {
                    int a = (bp == 1) ? (pr * 2) : pr;
                    int c = (bp == 1) ? (pr * 2 + 1) : (pr + 2);
                    u64 ax = xv[a], ay = yv[a], bx = xv[c], by = yv[c];
                    xv[a] = fma2(u0x, ax, fma2(nu0y, ay, fma2(u1x, bx, mul2(nu1y, by))));
                    yv[a] = fma2(u0x, ay, fma2(u0y, ax, fma2(u1x, by, mul2(u1y, bx))));
                    xv[c] = fma2(u2x, ax, fma2(nu2y, ay, fma2(u3x, bx, mul2(nu3y, by))));
                    yv[c] = fma2(u2x, ay, fma2(u2y, ax, fma2(u3x, by, mul2(u3y, bx))));
                }
            } else {
                u64 Ax = pack2(u0.x, u3.x), Ay = pack2(u0.y, u3.y), nAy = pack2(-u0.y, -u3.y);
                u64 Bx = pack2(u1.x, u2.x), By = pack2(u1.y, u2.y), nBy = pack2(-u1.y, -u2.y);
                #pragma unroll
                for (int v = 0; v < 4; v++) {
                    u64 xs_ = swap2(xv[v]);
                    u64 ys_ = swap2(yv[v]);
                    u64 nx = fma2(Ax, xv[v], fma2(nAy, yv[v], fma2(Bx, xs_, mul2(nBy, ys_))));
                    u64 ny = fma2(Ax, yv[v], fma2(Ay, xv[v], fma2(Bx, ys_, mul2(By, xs_))));
                    xv[v] = nx; yv[v] = ny;
                }
            }
        }
        __syncwarp();
        #pragma unroll
        for (int v = 0; v < 4; v++) {
            float2 rx = unpack2(xv[v]), ry = unpack2(yv[v]);
            sre[w][(2 * v) * 32 + l]     = rx.x;
            sre[w][(2 * v + 1) * 32 + l] = rx.y;
            sim_[w][(2 * v) * 32 + l]     = ry.x;
            sim_[w][(2 * v + 1) * 32 + l] = ry.y;
        }
        __syncwarp();
        #pragma unroll
        for (int v = 0; v < 4; v++) {
            xv[v] = pack2(sre[w][rslot[2 * v]], sre[w][rslot[2 * v + 1]]);
            yv[v] = pack2(sim_[w][rslot[2 * v]], sim_[w][rslot[2 * v + 1]]);
        }
    }

    u64 pacc = mul2(xv[0], xv[0]);
    pacc = fma2(yv[0], yv[0], pacc);
    #pragma unroll
    for (int v = 1; v < 4; v++) {
        pacc = fma2(xv[v], xv[v], pacc);
        pacc = fma2(yv[v], yv[v], pacc);
    }
    float2 pp = unpack2(pacc);
    float P = pp.x + pp.y;

    float e0 = (l & 16) ? -P : P;
    float e1 = (l & 8)  ? -P : P;
    float e2 = (l & 4)  ? -P : P;
    float e3 = (l & 2)  ? -P : P;
    #pragma unroll
    for (int o = 16; o; o >>= 1) {
        e0 += __shfl_xor_sync(0xffffffffu, e0, o);
        e1 += __shfl_xor_sync(0xffffffffu, e1, o);
        e2 += __shfl_xor_sync(0xffffffffu, e2, o);
        e3 += __shfl_xor_sync(0xffffffffu, e3, o);
    }
    if (l == 0) {
        float inv = 1.f / nr;
        g_q4[b] = make_float4(e0 * inv, e1 * inv, e2 * inv, e3 * inv);
    }
}

// ---------------- K2: feature processor + adapter + fc1 + BN1 partials -------
// 64 samples per block, 256 threads, dynamic smem with aliased regions.
// Warp w computes outputs [8w, 8w+8) for all 64 samples (lane s and s+32),
// k packed pairwise into f32x2.
#define FEAT_SMEM (64*260*4 + 64*68*4 + 2048)

__global__ __launch_bounds__(256, 2) void k_feat(
    const float* __restrict__ x,
    const float* __restrict__ aW, const float* __restrict__ ab,
    const float* __restrict__ fW1, const float* __restrict__ fb1,
    const float* __restrict__ fW2, const float* __restrict__ fb2,
    const float* __restrict__ cW1, const float* __restrict__ cb1, int B)
{
    extern __shared__ __align__(16) char sm[];
    float (*xs)[260] = (float(*)[260])sm;                 // 66560 B (GEMM phase)
    float (*ws)[68]  = (float(*)[68])(sm + 66560);        // 17408 B
    float *cst       = (float*)(sm + 83968);              // 2016 B consts
    float *fw2s = cst;            // 256
    float *cw1s = cst + 256;      // 128
    float *fb1s = cst + 384;      // 64
    float *cb1s = cst + 448;      // 32
    float *fb2s = cst + 480;      // 4
    float *abs_ = cst + 484;      // 4
    float *aWs  = cst + 488;      // 16
    // aliased into xs region (only used after GEMM, post-sync):
    float (*h1s)[68] = (float(*)[68])sm;                  // 17408 B
    float (*hs)[8]   = (float(*)[8])(sm + 20480);         // 2048 B
    float (*ys)[33]  = (float(*)[33])(sm + 24576);        // 8448 B

    int tid = threadIdx.x;
    int S0 = blockIdx.x * 64;
    int w = tid >> 5, l = tid & 31;

    // load consts
    fw2s[tid] = fW2[tid];
    if (tid < 128) cw1s[tid] = cW1[tid];
    if (tid < 64)  fb1s[tid] = fb1[tid];
    if (tid < 32)  cb1s[tid] = cb1[tid];
    if (tid < 16)  aWs[tid]  = aW[tid];
    if (tid < 4) { fb2s[tid] = fb2[tid]; abs_[tid] = ab[tid]; }

    // load x tile: 64 samples x 256 (float4, coalesced)
    for (int i = tid; i < 64 * 64; i += 256) {
        int s = i >> 6, q = i & 63;
        ((float4*)&xs[s][0])[q] = ((const float4*)(x + (size_t)(S0 + s) * 256))[q];
    }

    // main GEMM: acc[sg][j] packs (even-k sum, odd-k sum)
    u64 acc[2][8];
    #pragma unroll
    for (int sg = 0; sg < 2; sg++)
        #pragma unroll
        for (int j = 0; j < 8; j++) acc[sg][j] = 0ull;

    for (int kc = 0; kc < 4; kc++) {
        __syncthreads();
        for (int i = tid; i < 64 * 16; i += 256) {
            int o = i >> 4, q = i & 15;
            ((float4*)&ws[o][0])[q] = ((const float4*)(fW1 + o * 256 + kc * 64))[q];
        }
        __syncthreads();
        const float4* xr0 = (const float4*)&xs[l][kc * 64];
        const float4* xr1 = (const float4*)&xs[l + 32][kc * 64];
        #pragma unroll
        for (int q = 0; q < 16; q++) {
            float4 a4 = xr0[q], b4 = xr1[q];
            u64 x0lo = pack2(a4.x, a4.y), x0hi = pack2(a4.z, a4.w);
            u64 x1lo = pack2(b4.x, b4.y), x1hi = pack2(b4.z, b4.w);
            #pragma unroll
            for (int j = 0; j < 8; j++) {
                float4 w4 = ((const float4*)&ws[w * 8 + j][0])[q];
                u64 wlo = pack2(w4.x, w4.y), whi = pack2(w4.z, w4.w);
                acc[0][j] = fma2(wlo, x0lo, acc[0][j]);
                acc[0][j] = fma2(whi, x0hi, acc[0][j]);
                acc[1][j] = fma2(wlo, x1lo, acc[1][j]);
                acc[1][j] = fma2(whi, x1hi, acc[1][j]);
            }
        }
    }
    __syncthreads();   // all warps done reading xs/ws before aliasing

    #pragma unroll
    for (int sg = 0; sg < 2; sg++) {
        int s = l + 32 * sg;
        #pragma unroll
        for (int j = 0; j < 8; j++) {
            float2 r = unpack2(acc[sg][j]);
            h1s[s][w * 8 + j] = fmaxf(r.x + r.y + fb1s[w * 8 + j], 0.f);
        }
    }
    __syncthreads();

    // head: tanh(fW2 @ h1 + fb2) + adapter(q)
    {
        int s = tid & 63, j = tid >> 6;   // j in 0..3
        float a = fb2s[j];
        const float4* hp = (const float4*)&h1s[s][0];
        const float4* wp = (const float4*)&fw2s[j * 64];
        #pragma unroll
        for (int q = 0; q < 16; q++) {
            float4 h = hp[q], wv = wp[q];
            a += h.x * wv.x + h.y * wv.y + h.z * wv.z + h.w * wv.w;
        }
        float cf = tanhf(a);
        float4 qv = g_q4[S0 + s];
        float qf = abs_[j] + aWs[j * 4 + 0] * qv.x + aWs[j * 4 + 1] * qv.y
                           + aWs[j * 4 + 2] * qv.z + aWs[j * 4 + 3] * qv.w;
        hs[s][j] = cf + qf;
    }
    __syncthreads();

    // cW1: 64 samples x 32 outputs
    for (int i = tid; i < 64 * 32; i += 256) {
        int s = i >> 5, o = i & 31;
        float vv = cb1s[o];
        #pragma unroll
        for (int k = 0; k < 4; k++) vv += hs[s][k] * cw1s[o * 4 + k];
        g_y1[(size_t)(S0 + s) * 32 + o] = vv;
        ys[s][o] = vv;
    }
    __syncthreads();

    if (tid < 32) {
        float su = 0.f, sq = 0.f;
        #pragma unroll
        for (int s = 0; s < 64; s++) {
            float vv = ys[s][tid];
            su += vv; sq += vv * vv;
        }
        g_part1[blockIdx.x * 64 + tid]      = su;
        g_part1[blockIdx.x * 64 + 32 + tid] = sq;
    }
}

// ---------------- K3: BN1 finalize + fc2 + [global barrier] + BN2 + tail -----
__global__ __launch_bounds__(256) void k_fc2tail(
    const float* __restrict__ cW2, const float* __restrict__ cb2,
    const float* __restrict__ g1,  const float* __restrict__ be1,
    const float* __restrict__ cW3, const float* __restrict__ cb3,
    const float* __restrict__ cW4, const float* __restrict__ cb4,
    const float* __restrict__ g2,  const float* __restrict__ be2,
    float* __restrict__ out, int B)
{
    __shared__ float w2s[512], b2s[16], bns[64];
    __shared__ float red1[4][64], tot1[64];
    __shared__ float wsum[8][32];
    __shared__ float w3s[128], b3s[8], w4s[8], bn2[32], tot2[32];
    int tid = threadIdx.x;

    // BN1 finalize from feat partials
    {
        int c = tid & 63, rp = tid >> 6;
        int NB = B / 64;
        float sv = 0.f;
        for (int bb = rp; bb < NB; bb += 4) sv += g_part1[bb * 64 + c];
        red1[rp][c] = sv;
    }
    for (int i = tid; i < 512; i += 256) w2s[i] = cW2[i];
    if (tid < 128) w3s[tid] = cW3[tid];
    if (tid < 16)  b2s[tid] = cb2[tid];
    if (tid < 8) { b3s[tid] = cb3[tid]; w4s[tid] = cW4[tid]; }
    __syncthreads();
    if (tid < 64) tot1[tid] = red1[0][tid] + red1[1][tid] + red1[2][tid] + red1[3][tid];
    __syncthreads();
    if (tid < 32) {
        float invB  = 1.f / (float)B;
        float mean  = tot1[tid] * invB;
        float var   = tot1[32 + tid] * invB - mean * mean;
        float scale = g1[tid] * rsqrtf(var + 1e-5f);
        bns[tid]      = scale;
        bns[32 + tid] = be1[tid] - mean * scale;
    }
    __syncthreads();

    int sidx = blockIdx.x * 256 + tid;
    float z[32];
    const float4* yp = (const float4*)(g_y1 + (size_t)sidx * 32);
    #pragma unroll
    for (int i = 0; i < 8; i++) {
        float4 u = yp[i];
        z[4 * i + 0] = fmaxf(u.x * bns[4 * i + 0] + bns[32 + 4 * i + 0], 0.f);
        z[4 * i + 1] = fmaxf(u.y * bns[4 * i + 1] + bns[32 + 4 * i + 1], 0.f);
        z[4 * i + 2] = fmaxf(u.z * bns[4 * i + 2] + bns[32 + 4 * i + 2], 0.f);
        z[4 * i + 3] = fmaxf(u.w * bns[4 * i + 3] + bns[32 + 4 * i + 3], 0.f);
    }
    float y2v[16];
    #pragma unroll
    for (int j = 0; j < 16; j++) {
        float a = b2s[j];
        #pragma unroll
        for (int o = 0; o < 32; o++) a += z[o] * w2s[j * 32 + o];
        y2v[j] = a;
    }

    // BN2 partials (y2 stays in registers)
    int lane = tid & 31, wp2 = tid >> 5;
    #pragma unroll
    for (int j = 0; j < 16; j++) {
        float su = y2v[j], sq = y2v[j] * y2v[j];
        #pragma unroll
        for (int o = 16; o; o >>= 1) {
            su += __shfl_xor_sync(0xffffffffu, su, o);
            sq += __shfl_xor_sync(0xffffffffu, sq, o);
        }
        if (lane == 0) { wsum[wp2][j] = su; wsum[wp2][16 + j] = sq; }
    }
    __syncthreads();
    if (tid < 32) {
        float sfull = 0.f;
        #pragma unroll
        for (int wi = 0; wi < 8; wi++) sfull += wsum[wi][tid];
        g_part2[blockIdx.x * 32 + tid] = sfull;
    }
    __syncthreads();

    // ---- device-wide barrier (all gridDim.x blocks resident; self-resetting)
    if (tid == 0) {
        __threadfence();
        atomicAdd(&g_arrive, 1u);
        while (atomicAdd(&g_arrive, 0u) < gridDim.x) { }
        unsigned d = atomicAdd(&g_depart, 1u) + 1u;
        if (d == gridDim.x) {
            atomicExch(&g_arrive, 0u);
            atomicExch(&g_depart, 0u);
        }
    }
    __syncthreads();

    // BN2 finalize
    if (tid < 32) {
        float sv = 0.f;
        int NB2 = B / 256;
        for (int bb = 0; bb < NB2; bb++) sv += __ldcg(&g_part2[bb * 32 + tid]);
        tot2[tid] = sv;
    }
    __syncthreads();
    if (tid < 16) {
        float invB  = 1.f / (float)B;
        float mean  = tot2[tid] * invB;
        float var   = tot2[16 + tid] * invB - mean * mean;
        float scale = g2[tid] * rsqrtf(var + 1e-5f);
        bn2[tid]      = scale;
        bn2[16 + tid] = be2[tid] - mean * scale;
    }
    __syncthreads();

    // tail: BN2 + relu + fc3 + relu + fc4 + sigmoid (from registers)
    float z2[16];
    #pragma unroll
    for (int j = 0; j < 16; j++)
        z2[j] = fmaxf(y2v[j] * bn2[j] + bn2[16 + j], 0.f);
    float o = cb4[0];
    #pragma unroll
    for (int j = 0; j < 8; j++) {
        float a = b3s[j];
        #pragma unroll
        for (int k = 0; k < 16; k++) a += z2[k] * w3s[j * 16 + k];
        o += fmaxf(a, 0.f) * w4s[j];
    }
    out[sidx] = 1.f / (1.f + expf(-o));
}

// ---------------- launch ------------------------------------------------------
extern "C" void kernel_launch(void* const* d_in, const int* in_sizes, int n_in,
                              void* d_out, int out_size) {
    const float* x    = (const float*)d_in[0];
    const float* qw   = (const float*)d_in[1];
    const float* aW   = (const float*)d_in[2];
    const float* ab   = (const float*)d_in[3];
    const float* fW1  = (const float*)d_in[4];
    const float* fb1  = (const float*)d_in[5];
    const float* fW2  = (const float*)d_in[6];
    const float* fb2  = (const float*)d_in[7];
    const float* cW1  = (const float*)d_in[8];
    const float* cb1  = (const float*)d_in[9];
    const float* g1   = (const float*)d_in[10];
    const float* be1  = (const float*)d_in[11];
    const float* cW2  = (const float*)d_in[12];
    const float* cb2  = (const float*)d_in[13];
    const float* g2   = (const float*)d_in[14];
    const float* be2  = (const float*)d_in[15];
    const float* cW3  = (const float*)d_in[16];
    const float* cb3  = (const float*)d_in[17];
    const float* cW4  = (const float*)d_in[18];
    const float* cb4  = (const float*)d_in[19];

    int B = in_sizes[0] / 256;

    static_assert(FEAT_SMEM <= 112 * 1024, "smem budget");
    cudaFuncSetAttribute(k_feat, cudaFuncAttributeMaxDynamicSharedMemorySize, FEAT_SMEM);

    k_qsim<<<B / 8, 256>>>(x, qw, B);
    k_feat<<<B / 64, 256, FEAT_SMEM>>>(x, aW, ab, fW1, fb1, fW2, fb2, cW1, cb1, B);
    k_fc2tail<<<B / 256, 256>>>(cW2, cb2, g1, be1, cW3, cb3, cW4, cb4, g2, be2,
                                (float*)d_out, B);
}